// round 7
// baseline (speedup 1.0000x reference)
#include <cuda_runtime.h>
#include <math.h>

// ---------------- problem constants ----------------
#define IN_CH   512
#define OUT_CH  512
#define KK      9
#define STYLE_DIM 512
#define B_SZ    8
#define HW      64
#define NPIX    4096              // 64*64
#define CONV_SCALE (1.0f / 67.8822509939086f)   // 1/sqrt(512*9)
#define MOD_SCALE  (1.0f / 22.627416997969522f) // 1/sqrt(512)
#define EPSV 1e-8f

// ---------------- device scratch (no allocs allowed) ----------------
__device__ float g_w5[IN_CH * KK * OUT_CH];   // layout [i][t][o]  (o contiguous)
__device__ float g_W2t[IN_CH * OUT_CH];       // layout [i][o]     (o contiguous)
__device__ float g_sc[B_SZ * IN_CH];          // CONV_SCALE * s[b,i]
__device__ float g_demod[B_SZ * OUT_CH];

// ---------------- f32x2 helpers (sm_103a packed fp32) ----------------
__device__ __forceinline__ unsigned long long pk2(float a, float b) {
    unsigned long long r;
    asm("mov.b64 %0, {%1,%2};" : "=l"(r) : "f"(a), "f"(b));
    return r;
}
__device__ __forceinline__ void unpk2(unsigned long long v, float& lo, float& hi) {
    asm("mov.b64 {%0,%1}, %2;" : "=f"(lo), "=f"(hi) : "l"(v));
}
__device__ __forceinline__ void fma2(unsigned long long& d, unsigned long long a,
                                     unsigned long long b) {
    asm("fma.rn.f32x2 %0, %1, %2, %0;" : "+l"(d) : "l"(a), "l"(b));
}

// ======================================================================
// Kernel 1: w5[o,i,t] = weight + relu(A @ relu(B @ B_inst)); also W2[o,i]
// grid 512 (one block per o), 256 threads
// ======================================================================
__global__ __launch_bounds__(256) void prep_w5_kernel(
    const float* __restrict__ weight,     // [1,512,512,3,3]
    const float* __restrict__ llB,        // [512,4]
    const float* __restrict__ llBinst,    // [4,4,9]
    const float* __restrict__ llA)        // [512,4]
{
    const int o = blockIdx.x;
    const int tid = threadIdx.x;
    __shared__ float Bo[4];
    __shared__ float Bm[4][9];

    if (tid < 4) Bo[tid] = llB[o * 4 + tid];
    __syncthreads();
    if (tid < 36) {
        int b_ = tid / 9, t = tid - b_ * 9;
        float acc = 0.f;
#pragma unroll
        for (int r = 0; r < 4; r++) acc += Bo[r] * llBinst[(b_ * 4 + r) * 9 + t];
        Bm[b_][t] = fmaxf(acc, 0.f);
    }
    __syncthreads();

    for (int i = tid; i < IN_CH; i += 256) {
        float A0 = llA[i * 4 + 0], A1 = llA[i * 4 + 1];
        float A2 = llA[i * 4 + 2], A3 = llA[i * 4 + 3];
        float w2sum = 0.f;
#pragma unroll
        for (int t = 0; t < 9; t++) {
            float add = fmaxf(A0 * Bm[0][t] + A1 * Bm[1][t] + A2 * Bm[2][t] + A3 * Bm[3][t], 0.f);
            float w = weight[(o * IN_CH + i) * 9 + t] + add;
            g_w5[(i * 9 + t) * OUT_CH + o] = w;
            w2sum += w * w;
        }
        g_W2t[i * OUT_CH + o] = w2sum;
    }
}

// ======================================================================
// Kernel 2: sc[b,i] = CONV_SCALE * (MOD_SCALE * style @ w_fc.T + b_fc)
// grid 64: (b, i-chunk of 64); 512 threads: one warp per i, lanes over j
// ======================================================================
__global__ __launch_bounds__(512) void prep_s_kernel(
    const float* __restrict__ style,    // [8,512]
    const float* __restrict__ modW,     // [512,512]
    const float* __restrict__ modB,     // [512]
    const float* __restrict__ fcA,      // [512,4]
    const float* __restrict__ fcB,      // [512,4]
    const float* __restrict__ fcBias)   // [512]
{
    const int b  = blockIdx.x >> 3;
    const int i0 = (blockIdx.x & 7) << 6;
    const int tid = threadIdx.x;
    __shared__ float sty[STYLE_DIM];
    sty[tid] = style[b * STYLE_DIM + tid];
    __syncthreads();

    const int warp = tid >> 5, lane = tid & 31;
    for (int ii = warp; ii < 64; ii += 16) {
        const int i = i0 + ii;
        float4 fb = *(const float4*)&fcB[i * 4];
        float acc = 0.f;
        for (int j = lane; j < STYLE_DIM; j += 32) {
            float4 fa = *(const float4*)&fcA[j * 4];
            float wfc = modW[i * STYLE_DIM + j] +
                        (fb.x * fa.x + fb.y * fa.y + fb.z * fa.z + fb.w * fa.w);
            acc += sty[j] * wfc;
        }
#pragma unroll
        for (int off = 16; off; off >>= 1) acc += __shfl_xor_sync(0xFFFFFFFFu, acc, off);
        if (lane == 0) {
            float s = acc * MOD_SCALE + modB[i] + fcBias[i];
            g_sc[b * IN_CH + i] = s * CONV_SCALE;
        }
    }
}

// ======================================================================
// Kernel 3: demod[b,o] = rsqrt(sum_i sc[b,i]^2 * W2[o,i] + eps)
// ======================================================================
__global__ __launch_bounds__(256) void prep_demod_kernel()
{
    const int id = blockIdx.x * 256 + threadIdx.x;
    const int b = id >> 9, o = id & 511;
    const float* scp = &g_sc[b * IN_CH];
    float acc = 0.f;
#pragma unroll 8
    for (int i = 0; i < IN_CH; i++) {
        float sv = scp[i];
        acc = fmaf(sv * sv, g_W2t[i * OUT_CH + o], acc);
    }
    g_demod[b * OUT_CH + o] = rsqrtf(acc + EPSV);
}

// ======================================================================
// Kernel 4: main conv.
//   out[b,o,y,x] = demod[b,o] * sum_{i,t} w5[o,i,t] * sc[b,i] * in[...]
// Block: (b, 64 o-channels, 2 output rows x 64 wide). 256 threads.
//   ty = tid/16 -> o = o0 + 4*ty .. +3
//   tx = tid%16 -> pixel pairs j=tx (px 2tx,2tx+1) and j=tx+16 (px +32,+33)
// SMEM holds PRE-PACKED f32x2 operands:
//   sWP[ic][t][o']       = (w,w)                 -> LDS.128 gives 2 packed wts
//   sInP[ic][row][kw][j] = (in[2j+kw-1],in[2j+kw])*sc -> LDS.64 per tap
// Hot loop per (ic,t): 2x LDS.128 + 4x LDS.64 + 16x FFMA2. No register packing.
// ======================================================================
#define ICB 4
__global__ __launch_bounds__(256) void conv_kernel(
    const float* __restrict__ input,   // [8,512,64,64]
    float* __restrict__ out)           // [8,512,64,64]
{
    const int b  = blockIdx.z;
    const int o0 = blockIdx.y << 6;
    const int y0 = blockIdx.x << 1;
    const int tid = threadIdx.x;
    const int tx = tid & 15;
    const int ty = tid >> 4;

    __shared__ unsigned long long sWP[ICB][9][64];      // 18432 B
    __shared__ unsigned long long sInP[ICB][4][3][32];  // 12288 B
    __shared__ float sSc[IN_CH];                        // 2048 B

    unsigned long long acc[4][2][2];
#pragma unroll
    for (int a = 0; a < 4; a++)
#pragma unroll
        for (int r = 0; r < 2; r++) { acc[a][r][0] = 0ull; acc[a][r][1] = 0ull; }

    const float* inB = input + (size_t)b * IN_CH * NPIX;

    // cache per-channel scales in smem once
    sSc[tid]       = g_sc[b * IN_CH + tid];
    sSc[tid + 256] = g_sc[b * IN_CH + tid + 256];

#pragma unroll 1
    for (int ic0 = 0; ic0 < IN_CH; ic0 += ICB) {
        __syncthreads();
        // ---- weights: 4*9*64 = 2304 u64, 9 per thread, coalesced over o ----
#pragma unroll
        for (int l = 0; l < 9; l++) {
            int e = tid + 256 * l;
            int op   = e & 63;
            int rest = e >> 6;          // 0..35
            int t  = rest % 9;
            int ic = rest / 9;
            float w = g_w5[(ic0 + ic) * (9 * OUT_CH) + t * OUT_CH + o0 + op];
            sWP[ic][t][op] = pk2(w, w);
        }
        // ---- inputs: 3kw * 4ic * 4rows * 32pairs = 1536 u64, 6 per thread ----
#pragma unroll
        for (int l = 0; l < 6; l++) {
            int e   = tid + 256 * l;
            int kw  = e >> 9;           // 0..2
            int rem = e & 511;
            int ic  = rem >> 7;
            int row = (rem >> 5) & 3;
            int j   = rem & 31;
            int y  = y0 - 1 + row;
            int x0 = 2 * j + kw - 1;
            float s = sSc[ic0 + ic];
            const float* base = inB + (ic0 + ic) * NPIX + y * 64;
            float v0 = 0.f, v1 = 0.f;
            if ((unsigned)y < 64u) {
                if ((unsigned)x0 < 64u)       v0 = base[x0]     * s;
                if ((unsigned)(x0 + 1) < 64u) v1 = base[x0 + 1] * s;
            }
            sInP[ic][row][kw][j] = pk2(v0, v1);
        }
        __syncthreads();

        // ---- compute ----
#pragma unroll
        for (int ic = 0; ic < ICB; ic++) {
#pragma unroll
            for (int t = 0; t < 9; t++) {
                const int kh = t / 3;
                const int kw = t - kh * 3;
                ulonglong2 wa = *(const ulonglong2*)&sWP[ic][t][ty << 2];
                ulonglong2 wb = *(const ulonglong2*)&sWP[ic][t][(ty << 2) + 2];
#pragma unroll
                for (int r = 0; r < 2; r++) {
                    unsigned long long p01 = sInP[ic][r + kh][kw][tx];
                    unsigned long long p23 = sInP[ic][r + kh][kw][tx + 16];
                    fma2(acc[0][r][0], wa.x, p01);  fma2(acc[0][r][1], wa.x, p23);
                    fma2(acc[1][r][0], wa.y, p01);  fma2(acc[1][r][1], wa.y, p23);
                    fma2(acc[2][r][0], wb.x, p01);  fma2(acc[2][r][1], wb.x, p23);
                    fma2(acc[3][r][0], wb.y, p01);  fma2(acc[3][r][1], wb.y, p23);
                }
            }
        }
    }

    // ---- epilogue: apply demod, vectorized stores (pairs are adjacent px) ----
#pragma unroll
    for (int uo = 0; uo < 4; uo++) {
        const int o = o0 + (ty << 2) + uo;
        const float dm = g_demod[b * OUT_CH + o];
#pragma unroll
        for (int r = 0; r < 2; r++) {
            float* op = out + (((size_t)b * OUT_CH + o) * 64 + (y0 + r)) * 64;
            float lo, hi;
            unpk2(acc[uo][r][0], lo, hi);
            *(float2*)(op + 2 * tx)      = make_float2(lo * dm, hi * dm);
            unpk2(acc[uo][r][1], lo, hi);
            *(float2*)(op + 2 * tx + 32) = make_float2(lo * dm, hi * dm);
        }
    }
}

// ======================================================================
extern "C" void kernel_launch(void* const* d_in, const int* in_sizes, int n_in,
                              void* d_out, int out_size)
{
    const float* input   = (const float*)d_in[0];
    const float* style   = (const float*)d_in[1];
    const float* weight  = (const float*)d_in[2];
    const float* llB     = (const float*)d_in[3];
    const float* llBinst = (const float*)d_in[4];
    const float* llA     = (const float*)d_in[5];
    const float* modW    = (const float*)d_in[6];
    const float* modB    = (const float*)d_in[7];
    const float* fcA     = (const float*)d_in[8];
    const float* fcB     = (const float*)d_in[9];
    const float* fcBias  = (const float*)d_in[10];
    float* out = (float*)d_out;

    prep_w5_kernel<<<512, 256>>>(weight, llB, llBinst, llA);
    prep_s_kernel<<<64, 512>>>(style, modW, modB, fcA, fcB, fcBias);
    prep_demod_kernel<<<16, 256>>>();
    conv_kernel<<<dim3(32, 8, 8), 256>>>(input, out);
}